// round 2
// baseline (speedup 1.0000x reference)
#include <cuda_runtime.h>
#include <cuda_bf16.h>

// online_72344429134228: sequential online logistic-SGD scan.
//   theta_{k+1} = theta_k + ETA * x_k / (1 + exp(<x_k, theta_k>))
// D=2048, N=16384. Strictly sequential scalar recurrence -> single persistent
// CTA, theta (as phi = theta/2) in registers, SHFL butterfly warp reduce,
// tanh-based sigmoid, 4-deep register prefetch ring for x rows,
// double-buffered warp sums with a single __syncthreads per iteration.
//
// Half-scale substitution: phi = theta/2.
//   h = <x, phi> = pred/2
//   t = tanh(h)  =>  sigma(-pred) = 0.5*(1 - t)
//   theta += ETA*0.5*(1-t)*x  =>  phi += 0.25*ETA*(1-t)*x
//   output theta = 2*phi.

#define DDIM 2048
#define NSTEPS 16384
#define NTHREADS 256
#define NWARPS (NTHREADS / 32)
#define ETA 0.01f
#define PF 4
#define VPT (DDIM / NTHREADS / 4)   // float4s per thread = 2

__device__ __forceinline__ float fast_tanh(float x) {
    float r;
    asm("tanh.approx.f32 %0, %1;" : "=f"(r) : "f"(x));
    return r;
}

__global__ __launch_bounds__(NTHREADS, 1)
void online_sgd_kernel(const float* __restrict__ theta0,
                       const float* __restrict__ xs,
                       float* __restrict__ out) {
    __shared__ float wsum[2][8];   // 8 warp sums, double buffered

    const int tid  = threadIdx.x;
    const int w    = tid >> 5;
    const int lane = tid & 31;

    // phi = theta/2, resident in registers: thread t owns elements
    // {t, t+256} in float4 units (i.e. floats 4t..4t+3 and 1024+4t..1024+4t+3)
    const float4* th4 = reinterpret_cast<const float4*>(theta0);
    float4 f0 = th4[tid];
    float4 f1 = th4[tid + NTHREADS];
    f0.x *= 0.5f; f0.y *= 0.5f; f0.z *= 0.5f; f0.w *= 0.5f;
    f1.x *= 0.5f; f1.y *= 0.5f; f1.z *= 0.5f; f1.w *= 0.5f;

    const float4* x4 = reinterpret_cast<const float4*>(xs);  // [NSTEPS][512]

    // prefetch ring: x rows k .. k+PF-1 (two float4 per thread per row)
    float4 xa[PF], xb[PF];
#pragma unroll
    for (int i = 0; i < PF; i++) {
        xa[i] = x4[(size_t)i * (DDIM / 4) + tid];
        xb[i] = x4[(size_t)i * (DDIM / 4) + NTHREADS + tid];
    }

#pragma unroll 2
    for (int k = 0; k < NSTEPS; k++) {
        const float4 x0 = xa[k & (PF - 1)];
        const float4 x1 = xb[k & (PF - 1)];

        // issue prefetch for row k+PF (clamped; branch-free, deterministic)
        int kp = k + PF;
        if (kp >= NSTEPS) kp = NSTEPS - 1;
        xa[k & (PF - 1)] = x4[(size_t)kp * (DDIM / 4) + tid];
        xb[k & (PF - 1)] = x4[(size_t)kp * (DDIM / 4) + NTHREADS + tid];

        // partial half-dot over this thread's 8 elements (4 parallel chains)
        float p0 = x0.x * f0.x;
        float p1 = x0.z * f0.z;
        float q0 = x1.x * f1.x;
        float q1 = x1.z * f1.z;
        p0 = fmaf(x0.y, f0.y, p0);
        p1 = fmaf(x0.w, f0.w, p1);
        q0 = fmaf(x1.y, f1.y, q0);
        q1 = fmaf(x1.w, f1.w, q1);
        float p = (p0 + p1) + (q0 + q1);

        // warp butterfly reduction (5 x SHFL.BFLY)
        p += __shfl_xor_sync(0xffffffffu, p, 16);
        p += __shfl_xor_sync(0xffffffffu, p, 8);
        p += __shfl_xor_sync(0xffffffffu, p, 4);
        p += __shfl_xor_sync(0xffffffffu, p, 2);
        p += __shfl_xor_sync(0xffffffffu, p, 1);
        if (lane == 0) wsum[k & 1][w] = p;
        __syncthreads();

        // every thread reduces the 8 warp sums (broadcast LDS, no 2nd barrier;
        // values consumed before next iteration's barrier orders the WAR)
        const float4* ws4 = reinterpret_cast<const float4*>(wsum[k & 1]);
        float4 a = ws4[0], b = ws4[1];
        float h = ((a.x + a.y) + (a.z + a.w)) + ((b.x + b.y) + (b.z + b.w));

        // coeff for phi-update: 0.25*ETA*(1 - tanh(h))
        float t = fast_tanh(h);
        float c = fmaf(t, -0.25f * ETA, 0.25f * ETA);

        f0.x = fmaf(c, x0.x, f0.x);
        f0.y = fmaf(c, x0.y, f0.y);
        f0.z = fmaf(c, x0.z, f0.z);
        f0.w = fmaf(c, x0.w, f0.w);
        f1.x = fmaf(c, x1.x, f1.x);
        f1.y = fmaf(c, x1.y, f1.y);
        f1.z = fmaf(c, x1.z, f1.z);
        f1.w = fmaf(c, x1.w, f1.w);
    }

    // output theta = 2*phi
    float4 o0 = make_float4(2.f * f0.x, 2.f * f0.y, 2.f * f0.z, 2.f * f0.w);
    float4 o1 = make_float4(2.f * f1.x, 2.f * f1.y, 2.f * f1.z, 2.f * f1.w);
    reinterpret_cast<float4*>(out)[tid] = o0;
    reinterpret_cast<float4*>(out)[tid + NTHREADS] = o1;
}

extern "C" void kernel_launch(void* const* d_in, const int* in_sizes, int n_in,
                              void* d_out, int out_size) {
    const float* theta = (const float*)d_in[0];
    const float* xs    = (const float*)d_in[1];
    // robust to input ordering: theta has DDIM elements
    if (in_sizes[0] != DDIM) {
        theta = (const float*)d_in[1];
        xs    = (const float*)d_in[0];
    }
    online_sgd_kernel<<<1, NTHREADS>>>(theta, xs, (float*)d_out);
}

// round 4
// speedup vs baseline: 1.3943x; 1.3943x over previous
#include <cuda_runtime.h>
#include <cuda_bf16.h>

// online_72344429134228: sequential online logistic-SGD scan.
//   theta_{k+1} = theta_k + ETA * x_k / (1 + exp(<x_k, theta_k>))
// D=2048, N=16384. Strictly sequential scalar recurrence -> single persistent
// CTA, theta (as phi = theta/2) in registers, SHFL butterfly warp reduce,
// tanh-based sigmoid, 4-deep register prefetch ring for x rows,
// double-buffered warp sums with a single __syncthreads per iteration.
//
// Half-scale substitution: phi = theta/2.
//   h = <x, phi> = pred/2
//   t = tanh(h)  =>  sigma(-pred) = 0.5*(1 - t)
//   theta += ETA*0.5*(1-t)*x  =>  phi += 0.25*ETA*(1-t)*x
//   output theta = 2*phi.

#define DDIM 2048
#define NSTEPS 16384
#define NTHREADS 256
#define NWARPS (NTHREADS / 32)
#define ETA 0.01f
#define PF 4
#define VPT (DDIM / NTHREADS / 4)   // float4s per thread = 2

__device__ __forceinline__ float fast_tanh(float x) {
    float r;
    asm("tanh.approx.f32 %0, %1;" : "=f"(r) : "f"(x));
    return r;
}

__global__ __launch_bounds__(NTHREADS, 1)
void online_sgd_kernel(const float* __restrict__ theta0,
                       const float* __restrict__ xs,
                       float* __restrict__ out) {
    __shared__ float wsum[2][8];   // 8 warp sums, double buffered

    const int tid  = threadIdx.x;
    const int w    = tid >> 5;
    const int lane = tid & 31;

    // phi = theta/2, resident in registers: thread t owns elements
    // {t, t+256} in float4 units (i.e. floats 4t..4t+3 and 1024+4t..1024+4t+3)
    const float4* th4 = reinterpret_cast<const float4*>(theta0);
    float4 f0 = th4[tid];
    float4 f1 = th4[tid + NTHREADS];
    f0.x *= 0.5f; f0.y *= 0.5f; f0.z *= 0.5f; f0.w *= 0.5f;
    f1.x *= 0.5f; f1.y *= 0.5f; f1.z *= 0.5f; f1.w *= 0.5f;

    const float4* x4 = reinterpret_cast<const float4*>(xs);  // [NSTEPS][512]

    // prefetch ring: x rows k .. k+PF-1 (two float4 per thread per row)
    float4 xa[PF], xb[PF];
#pragma unroll
    for (int i = 0; i < PF; i++) {
        xa[i] = x4[(size_t)i * (DDIM / 4) + tid];
        xb[i] = x4[(size_t)i * (DDIM / 4) + NTHREADS + tid];
    }

#pragma unroll 2
    for (int k = 0; k < NSTEPS; k++) {
        const float4 x0 = xa[k & (PF - 1)];
        const float4 x1 = xb[k & (PF - 1)];

        // issue prefetch for row k+PF (clamped; branch-free, deterministic)
        int kp = k + PF;
        if (kp >= NSTEPS) kp = NSTEPS - 1;
        xa[k & (PF - 1)] = x4[(size_t)kp * (DDIM / 4) + tid];
        xb[k & (PF - 1)] = x4[(size_t)kp * (DDIM / 4) + NTHREADS + tid];

        // partial half-dot over this thread's 8 elements (4 parallel chains)
        float p0 = x0.x * f0.x;
        float p1 = x0.z * f0.z;
        float q0 = x1.x * f1.x;
        float q1 = x1.z * f1.z;
        p0 = fmaf(x0.y, f0.y, p0);
        p1 = fmaf(x0.w, f0.w, p1);
        q0 = fmaf(x1.y, f1.y, q0);
        q1 = fmaf(x1.w, f1.w, q1);
        float p = (p0 + p1) + (q0 + q1);

        // warp butterfly reduction (5 x SHFL.BFLY)
        p += __shfl_xor_sync(0xffffffffu, p, 16);
        p += __shfl_xor_sync(0xffffffffu, p, 8);
        p += __shfl_xor_sync(0xffffffffu, p, 4);
        p += __shfl_xor_sync(0xffffffffu, p, 2);
        p += __shfl_xor_sync(0xffffffffu, p, 1);
        if (lane == 0) wsum[k & 1][w] = p;
        __syncthreads();

        // every thread reduces the 8 warp sums (broadcast LDS, no 2nd barrier;
        // values consumed before next iteration's barrier orders the WAR)
        const float4* ws4 = reinterpret_cast<const float4*>(wsum[k & 1]);
        float4 a = ws4[0], b = ws4[1];
        float h = ((a.x + a.y) + (a.z + a.w)) + ((b.x + b.y) + (b.z + b.w));

        // coeff for phi-update: 0.25*ETA*(1 - tanh(h))
        float t = fast_tanh(h);
        float c = fmaf(t, -0.25f * ETA, 0.25f * ETA);

        f0.x = fmaf(c, x0.x, f0.x);
        f0.y = fmaf(c, x0.y, f0.y);
        f0.z = fmaf(c, x0.z, f0.z);
        f0.w = fmaf(c, x0.w, f0.w);
        f1.x = fmaf(c, x1.x, f1.x);
        f1.y = fmaf(c, x1.y, f1.y);
        f1.z = fmaf(c, x1.z, f1.z);
        f1.w = fmaf(c, x1.w, f1.w);
    }

    // output theta = 2*phi
    float4 o0 = make_float4(2.f * f0.x, 2.f * f0.y, 2.f * f0.z, 2.f * f0.w);
    float4 o1 = make_float4(2.f * f1.x, 2.f * f1.y, 2.f * f1.z, 2.f * f1.w);
    reinterpret_cast<float4*>(out)[tid] = o0;
    reinterpret_cast<float4*>(out)[tid + NTHREADS] = o1;
}

extern "C" void kernel_launch(void* const* d_in, const int* in_sizes, int n_in,
                              void* d_out, int out_size) {
    const float* theta = (const float*)d_in[0];
    const float* xs    = (const float*)d_in[1];
    // robust to input ordering: theta has DDIM elements
    if (in_sizes[0] != DDIM) {
        theta = (const float*)d_in[1];
        xs    = (const float*)d_in[0];
    }
    online_sgd_kernel<<<1, NTHREADS>>>(theta, xs, (float*)d_out);
}

// round 6
// speedup vs baseline: 6.9223x; 4.9647x over previous
#include <cuda_runtime.h>
#include <cstdint>

// Blocked online logistic-SGD scan.
// Phase 1 (grid): band Gram  g_WB[m][j][r] = 0.5*<x_{32m+r}, x_{32(m-1)+j}>, j in [0,64)
//   (j<32: previous block; j>=32: intra block rows j-32).
// Phase 2 (4-CTA cluster): workers shard D=2048 into 512-col slices (update theta
//   slice with c^{(s-1)}, matvec d_{s+1} partials -> DSMEM push to CTA0) while CTA0
//   warp0 runs block s's sequential 32-step tanh chain and broadcasts c^{(s)}.
//   One cluster barrier per segment; double-buffered c / dpart.

#define DDIM 2048
#define NSTEPS 16384
#define BLK 32
#define NBLK (NSTEPS / BLK)   // 512
#define ETA 0.01f
#define NC 4
#define SLICE (DDIM / NC)     // 512
#define NTH 288               // warp0: chain (CTA0) / idle; warps 1-8: workers

__device__ float g_WB[(size_t)NBLK * 64 * BLK];   // 4 MB scratch

__device__ __forceinline__ float fast_tanh(float x) {
    float r; asm("tanh.approx.f32 %0, %1;" : "=f"(r) : "f"(x)); return r;
}
__device__ __forceinline__ uint32_t smem_u32(const void* p) {
    return (uint32_t)__cvta_generic_to_shared(p);
}
__device__ __forceinline__ uint32_t mapa_rk(uint32_t a, uint32_t rk) {
    uint32_t r; asm("mapa.shared::cluster.u32 %0, %1, %2;" : "=r"(r) : "r"(a), "r"(rk));
    return r;
}
__device__ __forceinline__ void st_cluster_f32(uint32_t a, float v) {
    asm volatile("st.shared::cluster.f32 [%0], %1;" :: "r"(a), "f"(v) : "memory");
}
__device__ __forceinline__ void cluster_sync_() {
    asm volatile("barrier.cluster.arrive.aligned;" ::: "memory");
    asm volatile("barrier.cluster.wait.aligned;" ::: "memory");
}

// ---------------- Phase 1: band Gram, 512 CTAs x 256 thr ----------------
__global__ __launch_bounds__(256) void gram_kernel(const float* __restrict__ xs) {
    __shared__ float Bs[64][65];
    const int m = blockIdx.x, t = threadIdx.x;
    const int r0 = (t & 7) * 4, j0 = (t >> 3) * 2;
    const int baserow = 32 * m - 32;
    float acc[4][2] = {{0.f,0.f},{0.f,0.f},{0.f,0.f},{0.f,0.f}};
    for (int ch = 0; ch < DDIM / 64; ch++) {
#pragma unroll
        for (int q = 0; q < 4; q++) {
            int id = t + 256 * q;
            int row = id >> 4, c4 = (id & 15) * 4;
            int arow = baserow + row;
            float4 v = make_float4(0.f, 0.f, 0.f, 0.f);
            if (arow >= 0)
                v = *(const float4*)(xs + (size_t)arow * DDIM + ch * 64 + c4);
            Bs[row][c4+0]=v.x; Bs[row][c4+1]=v.y; Bs[row][c4+2]=v.z; Bs[row][c4+3]=v.w;
        }
        __syncthreads();
#pragma unroll 8
        for (int d = 0; d < 64; d++) {
            float a0=Bs[32+r0+0][d], a1=Bs[32+r0+1][d], a2=Bs[32+r0+2][d], a3=Bs[32+r0+3][d];
            float b0=Bs[j0+0][d], b1=Bs[j0+1][d];
            acc[0][0]=fmaf(a0,b0,acc[0][0]); acc[1][0]=fmaf(a1,b0,acc[1][0]);
            acc[2][0]=fmaf(a2,b0,acc[2][0]); acc[3][0]=fmaf(a3,b0,acc[3][0]);
            acc[0][1]=fmaf(a0,b1,acc[0][1]); acc[1][1]=fmaf(a1,b1,acc[1][1]);
            acc[2][1]=fmaf(a2,b1,acc[2][1]); acc[3][1]=fmaf(a3,b1,acc[3][1]);
        }
        __syncthreads();
    }
    float* dst = g_WB + (size_t)m * (64 * BLK);
#pragma unroll
    for (int rr = 0; rr < 4; rr++)
#pragma unroll
        for (int jj = 0; jj < 2; jj++)
            dst[(j0 + jj) * BLK + (r0 + rr)] = 0.5f * acc[rr][jj];
}

// ---------------- Phase 2 helpers ----------------
__device__ __forceinline__ void matvec_push(const float* __restrict__ xs,
        const float* __restrict__ th, int blk, int wwarp, int lane,
        int colbase, uint32_t dpart_local) {
    const float4* th4 = (const float4*)th;
    float4 t0 = th4[lane], t1 = th4[lane+32], t2 = th4[lane+64], t3 = th4[lane+96];
    float s[4];
#pragma unroll
    for (int rr = 0; rr < 4; rr++) {
        const float4* xr = (const float4*)(xs + ((size_t)blk * BLK + 4*wwarp + rr) * DDIM + colbase);
        float4 a = xr[lane], b = xr[lane+32], c = xr[lane+64], d = xr[lane+96];
        float p0 = a.x*t0.x; p0=fmaf(a.y,t0.y,p0); p0=fmaf(a.z,t0.z,p0); p0=fmaf(a.w,t0.w,p0);
        float p1 = b.x*t1.x; p1=fmaf(b.y,t1.y,p1); p1=fmaf(b.z,t1.z,p1); p1=fmaf(b.w,t1.w,p1);
        float p2 = c.x*t2.x; p2=fmaf(c.y,t2.y,p2); p2=fmaf(c.z,t2.z,p2); p2=fmaf(c.w,t2.w,p2);
        float p3 = d.x*t3.x; p3=fmaf(d.y,t3.y,p3); p3=fmaf(d.z,t3.z,p3); p3=fmaf(d.w,t3.w,p3);
        s[rr] = (p0 + p1) + (p2 + p3);
    }
#pragma unroll
    for (int rr = 0; rr < 4; rr++) {
        s[rr] += __shfl_xor_sync(0xffffffffu, s[rr], 16);
        s[rr] += __shfl_xor_sync(0xffffffffu, s[rr], 8);
        s[rr] += __shfl_xor_sync(0xffffffffu, s[rr], 4);
        s[rr] += __shfl_xor_sync(0xffffffffu, s[rr], 2);
        s[rr] += __shfl_xor_sync(0xffffffffu, s[rr], 1);
    }
    if (lane == 0) {
        uint32_t dst = mapa_rk(dpart_local, 0);
#pragma unroll
        for (int rr = 0; rr < 4; rr++)
            st_cluster_f32(dst + (uint32_t)(4*wwarp + rr) * 4u, 0.5f * s[rr]);
    }
}

__device__ __forceinline__ void apply_update(const float* __restrict__ xs,
        float* __restrict__ th, const float* __restrict__ cp,
        int blk, int widx, int colbase) {
    float2 t = *(float2*)(th + 2*widx);
    const float* xp = xs + (size_t)blk * BLK * DDIM + colbase + 2*widx;
#pragma unroll 8
    for (int j = 0; j < BLK; j++) {
        float c = cp[j];
        float2 xv = *(const float2*)(xp + (size_t)j * DDIM);
        t.x = fmaf(c, xv.x, t.x);
        t.y = fmaf(c, xv.y, t.y);
    }
    *(float2*)(th + 2*widx) = t;
}

__device__ __forceinline__ void run_chain(int s, int lane,
        const float* __restrict__ dp, const float* __restrict__ cprev,
        uint32_t cslot_local) {
    const float* G = g_WB + (size_t)s * (64 * BLK);
    float Gc[BLK], Gi[BLK];
#pragma unroll
    for (int j = 0; j < BLK; j++) Gc[j] = G[j * BLK + lane];
#pragma unroll
    for (int j = 0; j < BLK; j++) Gi[j] = G[(BLK + j) * BLK + lane];
    float h = (dp[lane] + dp[BLK + lane]) + (dp[2*BLK + lane] + dp[3*BLK + lane]);
#pragma unroll
    for (int j = 0; j < BLK; j++) h = fmaf(cprev[j], Gc[j], h);
    float cl, ck = 0.f;
    {
        float t = fast_tanh(h);
        cl = fmaf(t, -0.5f * ETA, 0.5f * ETA);
        if (lane == 0) ck = cl;
    }
#pragma unroll
    for (int r = 1; r < BLK; r++) {
        float cb = __shfl_sync(0xffffffffu, cl, r - 1);
        h = fmaf(cb, Gi[r - 1], h);
        float t = fast_tanh(h);
        cl = fmaf(t, -0.5f * ETA, 0.5f * ETA);
        if (lane == r) ck = cl;
    }
    asm volatile("st.shared.f32 [%0], %1;" :: "r"(cslot_local), "f"(ck) : "memory");
#pragma unroll
    for (int rk = 1; rk < NC; rk++)
        st_cluster_f32(mapa_rk(cslot_local, (uint32_t)rk), ck);
}

// ---------------- Phase 2: cluster scan ----------------
__global__ __launch_bounds__(NTH, 1) __cluster_dims__(NC, 1, 1)
void scan_kernel(const float* __restrict__ theta0, const float* __restrict__ xs,
                 float* __restrict__ out) {
    __shared__ float th[SLICE];
    __shared__ float cbuf[2][BLK];
    __shared__ float dpart[2][NC][BLK];

    const int tid = threadIdx.x;
    uint32_t rank; asm("mov.u32 %0, %%cluster_ctarank;" : "=r"(rank));
    const int colbase = (int)rank * SLICE;
    const int wwarp = (tid >> 5) - 1;
    const int lane = tid & 31;

    for (int i = tid; i < SLICE; i += NTH) th[i] = theta0[colbase + i];
    if (tid < 64) ((float*)cbuf)[tid] = 0.f;
    __syncthreads();

    // priming: d_0 into dpart[0]
    if (tid >= 32)
        matvec_push(xs, th, 0, wwarp, lane, colbase, smem_u32(&dpart[0][rank][0]));
    cluster_sync_();

    for (int s = 0; s < NBLK; s++) {
        if (tid < 32) {
            if (rank == 0)
                run_chain(s, lane, &dpart[s & 1][0][0], cbuf[(s + 1) & 1],
                          smem_u32(&cbuf[s & 1][lane]));
        } else {
            if (s > 0) apply_update(xs, th, cbuf[(s + 1) & 1], s - 1, tid - 32, colbase);
            asm volatile("bar.sync 1, 256;" ::: "memory");
            if (s + 1 < NBLK)
                matvec_push(xs, th, s + 1, wwarp, lane, colbase,
                            smem_u32(&dpart[(s + 1) & 1][rank][0]));
        }
        cluster_sync_();
    }

    if (tid >= 32)
        apply_update(xs, th, cbuf[(NBLK - 1) & 1], NBLK - 1, tid - 32, colbase);
    __syncthreads();
    for (int i = tid; i < SLICE; i += NTH) out[colbase + i] = th[i];
}

extern "C" void kernel_launch(void* const* d_in, const int* in_sizes, int n_in,
                              void* d_out, int out_size) {
    const float* theta = (const float*)d_in[0];
    const float* xs    = (const float*)d_in[1];
    if (in_sizes[0] != DDIM) {
        theta = (const float*)d_in[1];
        xs    = (const float*)d_in[0];
    }
    gram_kernel<<<NBLK, 256>>>(xs);
    scan_kernel<<<NC, NTH>>>(theta, xs, (float*)d_out);
}